// round 11
// baseline (speedup 1.0000x reference)
#include <cuda_runtime.h>
#include <cuda_fp16.h>
#include <cuda_bf16.h>
#include <cstdint>
#include <math.h>

#define MDIM 16
#define KDIM 4096
#define NDIM 11008
#define GRP 128
#define NGROUPS 32           // KDIM / GRP
#define NTILE 16             // N rows per block
#define THREADS 256          // 8 warps: (n-half, k-quarter)
#define KPW 1024             // K per warp
#define NSTAGE 16            // k64 stages per warp
#define QSTAGE 4             // cp.async ring depth
#define STAGE_BYTES 1024     // 8 rows * 128B
#define NCHUNKS 128          // KDIM/32 k32 chunks

__device__ int g_dtype;                               // 0=fp16 1=bf16 2=f32
__device__ __align__(16) uint4 g_Aperm[NCHUNKS * 64]; // [chunk][2][32] fragment-ordered A (fp16)

// ---------------- dtype-generic helpers ----------------

template <int DT>
__device__ __forceinline__ float elt_to_f(const void* p, int i) {
    if (DT == 0) return __half2float(((const __half*)p)[i]);
    if (DT == 1) return __bfloat162float(((const __nv_bfloat16*)p)[i]);
    return ((const float*)p)[i];
}

__device__ __forceinline__ uint32_t bf2_to_h2(uint32_t b) {
    __nv_bfloat162 bb = *reinterpret_cast<__nv_bfloat162*>(&b);
    float2 f = __bfloat1622float2(bb);
    __half2 h = __float22half2_rn(f);
    return *reinterpret_cast<uint32_t*>(&h);
}

template <int DT>
__device__ __forceinline__ uint4 load8h(const void* p, int i) {
    if (DT == 0) {
        return __ldg(reinterpret_cast<const uint4*>((const __half*)p + i));
    } else if (DT == 1) {
        uint4 v = __ldg(reinterpret_cast<const uint4*>((const __nv_bfloat16*)p + i));
        uint4 r;
        r.x = bf2_to_h2(v.x); r.y = bf2_to_h2(v.y);
        r.z = bf2_to_h2(v.z); r.w = bf2_to_h2(v.w);
        return r;
    } else {
        float4 f0 = __ldg(reinterpret_cast<const float4*>((const float*)p + i));
        float4 f1 = __ldg(reinterpret_cast<const float4*>((const float*)p + i + 4));
        __half2 h0 = __float22half2_rn(make_float2(f0.x, f0.y));
        __half2 h1 = __float22half2_rn(make_float2(f0.z, f0.w));
        __half2 h2 = __float22half2_rn(make_float2(f1.x, f1.y));
        __half2 h3 = __float22half2_rn(make_float2(f1.z, f1.w));
        uint4 r;
        r.x = *reinterpret_cast<uint32_t*>(&h0);
        r.y = *reinterpret_cast<uint32_t*>(&h1);
        r.z = *reinterpret_cast<uint32_t*>(&h2);
        r.w = *reinterpret_cast<uint32_t*>(&h3);
        return r;
    }
}

template <int DT>
__device__ __forceinline__ void store_out(void* p, int i, float v) {
    if (DT == 0)      ((__half*)p)[i] = __float2half(v);
    else if (DT == 1) ((__nv_bfloat16*)p)[i] = __float2bfloat16(v);
    else              ((float*)p)[i] = v;
}

// ---------------- dtype detection (warp-level) ----------------
__device__ __forceinline__ int detect_dtype(const void* scales) {
    const int lane = threadIdx.x & 31;
    uint4 v = __ldg(reinterpret_cast<const uint4*>(scales) + lane);
    uint32_t w[4] = {v.x, v.y, v.z, v.w};
    float s0 = 0.f, s1 = 0.f, s2 = 0.f;
    #pragma unroll
    for (int j = 0; j < 4; ++j) {
        float2 fh = __half22float2(*reinterpret_cast<__half2*>(&w[j]));
        s0 += (isfinite(fh.x) ? fabsf(fh.x) : 1e15f) + (isfinite(fh.y) ? fabsf(fh.y) : 1e15f);
        float2 fb = __bfloat1622float2(*reinterpret_cast<__nv_bfloat162*>(&w[j]));
        s1 += (isfinite(fb.x) ? fabsf(fb.x) : 1e15f) + (isfinite(fb.y) ? fabsf(fb.y) : 1e15f);
        float ff = __uint_as_float(w[j]);
        s2 += (isfinite(ff) ? fabsf(ff) : 1e15f);
    }
    #pragma unroll
    for (int off = 16; off; off >>= 1) {
        s0 += __shfl_xor_sync(0xffffffffu, s0, off);
        s1 += __shfl_xor_sync(0xffffffffu, s1, off);
        s2 += __shfl_xor_sync(0xffffffffu, s2, off);
    }
    float sc0 = fabsf(logf(fmaxf(s0, 1e-30f) / 5.27f));
    float sc1 = fabsf(logf(fmaxf(s1, 1e-30f) / 5.27f));
    float sc2 = fabsf(logf(fmaxf(s2, 1e-30f) / 2.64f));
    const float TH = 1.2f;
    if (sc1 < TH) return 1;
    if (sc0 < TH) return 0;
    if (sc2 < TH) return 2;
    if (sc1 <= sc0 && sc1 <= sc2) return 1;
    return (sc0 <= sc2) ? 0 : 2;
}

// ---------------- prep: dtype + fragment-ordered A ----------------
template <int DT>
__device__ __forceinline__ void prep_body(const void* __restrict__ A) {
    const int it   = blockIdx.x;       // 0..127 (k32 chunk)
    const int lane = threadIdx.x;      // 0..31
    const int t = lane & 3, r = lane >> 2;
    const uint4 alo = load8h<DT>(A, r * KDIM + it * 32 + 8 * t);
    const uint4 ahi = load8h<DT>(A, (r + 8) * KDIM + it * 32 + 8 * t);
    g_Aperm[it * 64 + lane]      = make_uint4(alo.x, ahi.x, alo.y, ahi.y);
    g_Aperm[it * 64 + 32 + lane] = make_uint4(alo.z, ahi.z, alo.w, ahi.w);
}

__global__ void prep_kernel(const void* __restrict__ A, const void* __restrict__ scales) {
    const int dt = detect_dtype(scales);
    if (blockIdx.x == 0 && threadIdx.x == 0) g_dtype = dt;
    if (dt == 1)      prep_body<1>(A);
    else if (dt == 0) prep_body<0>(A);
    else              prep_body<2>(A);
}

// ---------------- core math helpers ----------------

__device__ __forceinline__ uint32_t dec_nib(uint32_t x) {
    uint32_t lo, r;
    asm("lop3.b32 %0, %1, 0x0000000F, 0x64006400, 0xEA;" : "=r"(lo) : "r"(x));
    uint32_t sh = x << 12;
    asm("lop3.b32 %0, %1, %2, 0x000F0000, 0xF8;" : "=r"(r) : "r"(lo), "r"(sh));
    return r;
}

__device__ __forceinline__ uint32_t dq_word(uint32_t dec, __half2 vs, __half2 vmz) {
    const __half2 h1024 = __halves2half2(__ushort_as_half(0x6400), __ushort_as_half(0x6400));
    __half2 hq = __hsub2(*reinterpret_cast<__half2*>(&dec), h1024);
    __half2 w  = __hfma2(hq, vs, vmz);
    return *reinterpret_cast<uint32_t*>(&w);
}

__device__ __forceinline__ void mma_16816(float* c,
                                          uint32_t a0, uint32_t a1, uint32_t a2, uint32_t a3,
                                          uint32_t b0, uint32_t b1) {
    asm volatile("mma.sync.aligned.m16n8k16.row.col.f32.f16.f16.f32 "
                 "{%0,%1,%2,%3}, {%4,%5,%6,%7}, {%8,%9}, {%0,%1,%2,%3};\n"
                 : "+f"(c[0]), "+f"(c[1]), "+f"(c[2]), "+f"(c[3])
                 : "r"(a0), "r"(a1), "r"(a2), "r"(a3), "r"(b0), "r"(b1));
}

__device__ __forceinline__ void cp16(uint32_t dst, const void* src) {
    asm volatile("cp.async.cg.shared.global [%0], [%1], 16;\n" :: "r"(dst), "l"(src));
}
__device__ __forceinline__ void cp_commit() {
    asm volatile("cp.async.commit_group;\n");
}
template <int N>
__device__ __forceinline__ void cp_wait() {
    asm volatile("cp.async.wait_group %0;\n" :: "n"(N));
}
__device__ __forceinline__ uint4 lds128(uint32_t addr) {
    uint4 v;
    asm volatile("ld.shared.v4.u32 {%0,%1,%2,%3}, [%4];"
                 : "=r"(v.x), "=r"(v.y), "=r"(v.z), "=r"(v.w) : "r"(addr));
    return v;
}

// shared memory: 32KB qbuf + 2KB p + 4.6KB red = 38.6KB static
__shared__ __align__(128) char sh_q[8][QSTAGE][STAGE_BYTES];
__shared__ __half2 sh_p[NGROUPS][NTILE];          // (s, -s*z) per (group, n)
__shared__ float sh_red[2][4][MDIM][9];           // [nh][kw][m][nl&7 (+pad)]

// q stage layout (per warp, k64 = 32 ints per row, 8 rows):
//   granule(ci 0..7, row 0..7): addr = ci*128 + row*16
//   cp instr j (2/stage): rows 4j..4j+3; each row's 128B = one line -> 4 lines/instr
//   read chunk kk: lane(t,r) reads slot kk*4+t, row r -> 32 distinct granules (512B)

template <int DT>
__device__ __forceinline__ void gptq_body(const int* __restrict__ qw,
                                          const void* __restrict__ scales,
                                          const void* __restrict__ zeros,
                                          const void* __restrict__ bias,
                                          void* __restrict__ out) {
    const int tid  = threadIdx.x;
    const int warp = tid >> 5;
    const int lane = tid & 31;
    const int t    = lane & 3;
    const int r    = lane >> 2;     // 0..7
    const int crow = lane >> 3;     // 0..3 (cp row-within-quad)
    const int ci   = lane & 7;      // 0..7 (cp 16B granule)
    const int kw   = warp & 3;      // k quarter
    const int nh   = warp >> 2;     // n half
    const int n0   = blockIdx.x * NTILE;
    const int nrow0 = n0 + nh * 8;

    const uint32_t qsm = (uint32_t)__cvta_generic_to_shared(&sh_q[warp][0][0]);

    // per-thread cp dst offsets / src pointers (2 instrs per stage)
    uint32_t dsto[2];
    const int* srcp[2];
    #pragma unroll
    for (int j = 0; j < 2; ++j) {
        const int row = j * 4 + crow;
        dsto[j] = (uint32_t)(ci * 128 + row * 16);
        srcp[j] = qw + (nrow0 + row) * (KDIM / 2) + kw * (KPW / 2) + ci * 4;
    }

    // prologue: 3 stages in flight
    #pragma unroll
    for (int s = 0; s < QSTAGE - 1; ++s) {
        const uint32_t sb = qsm + s * STAGE_BYTES;
        cp16(sb + dsto[0], srcp[0] + s * 32);
        cp16(sb + dsto[1], srcp[1] + s * 32);
        cp_commit();
    }

    // scales/zeros -> smem: (s, -s*z); 512 coalesced elements each
    {
        const int sbase = n0 * NGROUPS;
        #pragma unroll
        for (int jj = 0; jj < 2; ++jj) {
            const int i = tid * 2 + jj;          // 0..511
            const int n = i >> 5;
            const int g = i & 31;
            const float s = elt_to_f<DT>(scales, sbase + i);
            const float z = elt_to_f<DT>(zeros,  sbase + i);
            sh_p[g][n] = __halves2half2(__float2half(s), __float2half(-s * z));
        }
    }
    __syncthreads();

    float acc[4] = {0.f, 0.f, 0.f, 0.f};

    #pragma unroll 1
    for (int s = 0; s < NSTAGE; ++s) {
        const int gg = kw * 8 + (s >> 1);       // 128-k group = 2 stages
        const __half2 p = sh_p[gg][nh * 8 + r];
        const __half2 vs  = __half2half2(__low2half(p));
        const __half2 vmz = __half2half2(__high2half(p));

        cp_wait<QSTAGE - 2>();
        __syncwarp();
        const uint32_t sb = qsm + (s & (QSTAGE - 1)) * STAGE_BYTES;

        #pragma unroll
        for (int kk = 0; kk < 2; ++kk) {
            const int gchunk = kw * 32 + s * 2 + kk;
            const uint4 af0 = __ldg(g_Aperm + gchunk * 64 + lane);
            const uint4 af1 = __ldg(g_Aperm + gchunk * 64 + 32 + lane);

            const uint4 q = lds128(sb + (uint32_t)((kk * 4 + t) * 128 + r * 16));
            const uint32_t w0 = dq_word(dec_nib(q.x), vs, vmz);
            const uint32_t w1 = dq_word(dec_nib(q.y), vs, vmz);
            const uint32_t w2 = dq_word(dec_nib(q.z), vs, vmz);
            const uint32_t w3 = dq_word(dec_nib(q.w), vs, vmz);
            mma_16816(acc, af0.x, af0.y, af0.z, af0.w, w0, w1);
            mma_16816(acc, af1.x, af1.y, af1.z, af1.w, w2, w3);
        }

        const int nx = s + QSTAGE - 1;
        if (nx < NSTAGE) {
            const uint32_t db = qsm + (nx & (QSTAGE - 1)) * STAGE_BYTES;
            cp16(db + dsto[0], srcp[0] + nx * 32);
            cp16(db + dsto[1], srcp[1] + nx * 32);
        }
        cp_commit();
    }

    // cross-warp (k) reduction per n-half
    sh_red[nh][kw][r][2 * t]         = acc[0];
    sh_red[nh][kw][r][2 * t + 1]     = acc[1];
    sh_red[nh][kw][r + 8][2 * t]     = acc[2];
    sh_red[nh][kw][r + 8][2 * t + 1] = acc[3];
    __syncthreads();

    // 256 outputs, one per thread
    {
        const int m  = tid >> 4;     // 0..15
        const int nl = tid & 15;     // 0..15
        const int h  = nl >> 3;
        const int nn = nl & 7;
        float v = (sh_red[h][0][m][nn] + sh_red[h][1][m][nn])
                + (sh_red[h][2][m][nn] + sh_red[h][3][m][nn]);
        v += elt_to_f<DT>(bias, n0 + nl);
        store_out<DT>(out, m * NDIM + n0 + nl, v);
    }
}

__global__ __launch_bounds__(THREADS, 5)
void gptq_main_kernel(const int* __restrict__ qw,
                      const void* __restrict__ scales,
                      const void* __restrict__ zeros,
                      const void* __restrict__ bias,
                      void* __restrict__ out) {
    const int dt = g_dtype;
    if (dt == 1)      gptq_body<1>(qw, scales, zeros, bias, out);
    else if (dt == 0) gptq_body<0>(qw, scales, zeros, bias, out);
    else              gptq_body<2>(qw, scales, zeros, bias, out);
}

extern "C" void kernel_launch(void* const* d_in, const int* in_sizes, int n_in,
                              void* d_out, int out_size) {
    const void* A      = nullptr;
    const int*  qw     = nullptr;
    const void* scales = nullptr;
    const void* zeros  = nullptr;
    const void* bias   = nullptr;

    for (int i = 0; i < n_in; ++i) {
        const int sz = in_sizes[i];
        if (sz == MDIM * KDIM) {                    // 65536
            A = d_in[i];
        } else if (sz == NDIM * (KDIM / 2)) {       // 22544384
            qw = (const int*)d_in[i];
        } else if (sz == NDIM) {                    // 11008
            bias = d_in[i];
        } else if (sz == NDIM * NGROUPS) {          // 352256
            if (!scales) scales = d_in[i];
            else         zeros  = d_in[i];
        }
    }

    prep_kernel<<<NCHUNKS, 32>>>(A, scales);
    gptq_main_kernel<<<NDIM / NTILE, THREADS>>>(qw, scales, zeros, bias, d_out);
}

// round 12
// speedup vs baseline: 1.1141x; 1.1141x over previous
#include <cuda_runtime.h>
#include <cuda_fp16.h>
#include <cuda_bf16.h>
#include <cstdint>
#include <math.h>

#define MDIM 16
#define KDIM 4096
#define NDIM 11008
#define GRP 128
#define NGROUPS 32           // KDIM / GRP
#define NTILE 16             // N rows per block
#define NWARP 4              // warps per block, each owns K/4
#define KPW 1024             // K per warp
#define NSTAGE 16            // k64 stages per warp
#define QSTAGE 4             // cp.async ring depth
#define STAGE_BYTES 2048     // 16 rows * 128B
#define NCHUNKS 128          // KDIM/32 k32 chunks

__device__ int g_dtype;                               // 0=fp16 1=bf16 2=f32
__device__ __align__(16) uint4 g_Aperm[NCHUNKS * 64]; // [chunk][2][32] fragment-ordered A (fp16)

// ---------------- dtype-generic helpers ----------------

template <int DT>
__device__ __forceinline__ float elt_to_f(const void* p, int i) {
    if (DT == 0) return __half2float(((const __half*)p)[i]);
    if (DT == 1) return __bfloat162float(((const __nv_bfloat16*)p)[i]);
    return ((const float*)p)[i];
}

__device__ __forceinline__ uint32_t bf2_to_h2(uint32_t b) {
    __nv_bfloat162 bb = *reinterpret_cast<__nv_bfloat162*>(&b);
    float2 f = __bfloat1622float2(bb);
    __half2 h = __float22half2_rn(f);
    return *reinterpret_cast<uint32_t*>(&h);
}

template <int DT>
__device__ __forceinline__ uint4 load8h(const void* p, int i) {
    if (DT == 0) {
        return __ldg(reinterpret_cast<const uint4*>((const __half*)p + i));
    } else if (DT == 1) {
        uint4 v = __ldg(reinterpret_cast<const uint4*>((const __nv_bfloat16*)p + i));
        uint4 r;
        r.x = bf2_to_h2(v.x); r.y = bf2_to_h2(v.y);
        r.z = bf2_to_h2(v.z); r.w = bf2_to_h2(v.w);
        return r;
    } else {
        float4 f0 = __ldg(reinterpret_cast<const float4*>((const float*)p + i));
        float4 f1 = __ldg(reinterpret_cast<const float4*>((const float*)p + i + 4));
        __half2 h0 = __float22half2_rn(make_float2(f0.x, f0.y));
        __half2 h1 = __float22half2_rn(make_float2(f0.z, f0.w));
        __half2 h2 = __float22half2_rn(make_float2(f1.x, f1.y));
        __half2 h3 = __float22half2_rn(make_float2(f1.z, f1.w));
        uint4 r;
        r.x = *reinterpret_cast<uint32_t*>(&h0);
        r.y = *reinterpret_cast<uint32_t*>(&h1);
        r.z = *reinterpret_cast<uint32_t*>(&h2);
        r.w = *reinterpret_cast<uint32_t*>(&h3);
        return r;
    }
}

template <int DT>
__device__ __forceinline__ void store_out(void* p, int i, float v) {
    if (DT == 0)      ((__half*)p)[i] = __float2half(v);
    else if (DT == 1) ((__nv_bfloat16*)p)[i] = __float2bfloat16(v);
    else              ((float*)p)[i] = v;
}

// ---------------- dtype detection (warp-level) ----------------
__device__ __forceinline__ int detect_dtype(const void* scales) {
    const int lane = threadIdx.x & 31;
    uint4 v = __ldg(reinterpret_cast<const uint4*>(scales) + lane);
    uint32_t w[4] = {v.x, v.y, v.z, v.w};
    float s0 = 0.f, s1 = 0.f, s2 = 0.f;
    #pragma unroll
    for (int j = 0; j < 4; ++j) {
        float2 fh = __half22float2(*reinterpret_cast<__half2*>(&w[j]));
        s0 += (isfinite(fh.x) ? fabsf(fh.x) : 1e15f) + (isfinite(fh.y) ? fabsf(fh.y) : 1e15f);
        float2 fb = __bfloat1622float2(*reinterpret_cast<__nv_bfloat162*>(&w[j]));
        s1 += (isfinite(fb.x) ? fabsf(fb.x) : 1e15f) + (isfinite(fb.y) ? fabsf(fb.y) : 1e15f);
        float ff = __uint_as_float(w[j]);
        s2 += (isfinite(ff) ? fabsf(ff) : 1e15f);
    }
    #pragma unroll
    for (int off = 16; off; off >>= 1) {
        s0 += __shfl_xor_sync(0xffffffffu, s0, off);
        s1 += __shfl_xor_sync(0xffffffffu, s1, off);
        s2 += __shfl_xor_sync(0xffffffffu, s2, off);
    }
    float sc0 = fabsf(logf(fmaxf(s0, 1e-30f) / 5.27f));
    float sc1 = fabsf(logf(fmaxf(s1, 1e-30f) / 5.27f));
    float sc2 = fabsf(logf(fmaxf(s2, 1e-30f) / 2.64f));
    const float TH = 1.2f;
    if (sc1 < TH) return 1;
    if (sc0 < TH) return 0;
    if (sc2 < TH) return 2;
    if (sc1 <= sc0 && sc1 <= sc2) return 1;
    return (sc0 <= sc2) ? 0 : 2;
}

// ---------------- prep: dtype + fragment-ordered A ----------------
template <int DT>
__device__ __forceinline__ void prep_body(const void* __restrict__ A) {
    const int it   = blockIdx.x;       // 0..127 (k32 chunk)
    const int lane = threadIdx.x;      // 0..31
    const int t = lane & 3, r = lane >> 2;
    const uint4 alo = load8h<DT>(A, r * KDIM + it * 32 + 8 * t);
    const uint4 ahi = load8h<DT>(A, (r + 8) * KDIM + it * 32 + 8 * t);
    g_Aperm[it * 64 + lane]      = make_uint4(alo.x, ahi.x, alo.y, ahi.y);
    g_Aperm[it * 64 + 32 + lane] = make_uint4(alo.z, ahi.z, alo.w, ahi.w);
}

__global__ void prep_kernel(const void* __restrict__ A, const void* __restrict__ scales) {
    const int dt = detect_dtype(scales);
    if (blockIdx.x == 0 && threadIdx.x == 0) g_dtype = dt;
    if (dt == 1)      prep_body<1>(A);
    else if (dt == 0) prep_body<0>(A);
    else              prep_body<2>(A);
}

// ---------------- core math helpers ----------------

__device__ __forceinline__ uint32_t dec_nib(uint32_t x) {
    uint32_t lo, r;
    asm("lop3.b32 %0, %1, 0x0000000F, 0x64006400, 0xEA;" : "=r"(lo) : "r"(x));
    uint32_t sh = x << 12;
    asm("lop3.b32 %0, %1, %2, 0x000F0000, 0xF8;" : "=r"(r) : "r"(lo), "r"(sh));
    return r;
}

__device__ __forceinline__ uint32_t dq_word(uint32_t dec, __half2 vs, __half2 vmz) {
    const __half2 h1024 = __halves2half2(__ushort_as_half(0x6400), __ushort_as_half(0x6400));
    __half2 hq = __hsub2(*reinterpret_cast<__half2*>(&dec), h1024);
    __half2 w  = __hfma2(hq, vs, vmz);
    return *reinterpret_cast<uint32_t*>(&w);
}

__device__ __forceinline__ void mma_16816(float* c,
                                          uint32_t a0, uint32_t a1, uint32_t a2, uint32_t a3,
                                          uint32_t b0, uint32_t b1) {
    asm volatile("mma.sync.aligned.m16n8k16.row.col.f32.f16.f16.f32 "
                 "{%0,%1,%2,%3}, {%4,%5,%6,%7}, {%8,%9}, {%0,%1,%2,%3};\n"
                 : "+f"(c[0]), "+f"(c[1]), "+f"(c[2]), "+f"(c[3])
                 : "r"(a0), "r"(a1), "r"(a2), "r"(a3), "r"(b0), "r"(b1));
}

__device__ __forceinline__ void cp16(uint32_t dst, const void* src) {
    asm volatile("cp.async.cg.shared.global [%0], [%1], 16;\n" :: "r"(dst), "l"(src));
}
__device__ __forceinline__ void cp_commit() {
    asm volatile("cp.async.commit_group;\n");
}
template <int N>
__device__ __forceinline__ void cp_wait() {
    asm volatile("cp.async.wait_group %0;\n" :: "n"(N));
}
__device__ __forceinline__ uint4 lds128(uint32_t addr) {
    uint4 v;
    asm volatile("ld.shared.v4.u32 {%0,%1,%2,%3}, [%4];"
                 : "=r"(v.x), "=r"(v.y), "=r"(v.z), "=r"(v.w) : "r"(addr));
    return v;
}

// shared memory: 32KB qbuf + 2KB p + 4.4KB red = 38.4KB static
__shared__ __align__(128) char sh_q[NWARP][QSTAGE][STAGE_BYTES];
__shared__ __half2 sh_p[NGROUPS][NTILE];          // (s, -s*z) per (group, n)
__shared__ float sh_red[NWARP][MDIM][NTILE + 1];

// q stage layout (per warp, k64 = 32 ints per row, 16 rows):
//  granule(ci 0..7, row 0..15): addr = ci*256 + ((row ^ ((ci&3)<<1)) << 4)
//  cp instr j (4/stage): rows 4j..4j+3; each row's 128B = one line -> 4 lines/instr
//  read chunk kk, col c: slot = kk*4+t, row = c*8+r; XOR-rotate keeps each
//  8-lane phase on 8 distinct 16B granule columns (conflict-free).

template <int DT>
__device__ __forceinline__ void gptq_body(const int* __restrict__ qw,
                                          const void* __restrict__ scales,
                                          const void* __restrict__ zeros,
                                          const void* __restrict__ bias,
                                          void* __restrict__ out) {
    const int tid  = threadIdx.x;
    const int warp = tid >> 5;
    const int lane = tid & 31;
    const int t    = lane & 3;
    const int r    = lane >> 2;
    const int crow = lane >> 3;     // cp row-within-quad
    const int ci   = lane & 7;      // cp 16B-granule index
    const int n0   = blockIdx.x * NTILE;

    const uint32_t qsm = (uint32_t)__cvta_generic_to_shared(&sh_q[warp][0][0]);

    // per-thread cp dst offsets / src pointers (4 rows per stage)
    uint32_t dsto[4];
    const int* srcp[4];
    #pragma unroll
    for (int j = 0; j < 4; ++j) {
        const int row = j * 4 + crow;
        dsto[j] = (uint32_t)(ci * 256 + ((row ^ ((ci & 3) << 1)) << 4));
        srcp[j] = qw + (n0 + row) * (KDIM / 2) + warp * (KPW / 2) + ci * 4;
    }

    // prologue: 3 stages in flight
    #pragma unroll
    for (int s = 0; s < QSTAGE - 1; ++s) {
        const uint32_t sb = qsm + s * STAGE_BYTES;
        #pragma unroll
        for (int j = 0; j < 4; ++j) cp16(sb + dsto[j], srcp[j] + s * 32);
        cp_commit();
    }

    // scales/zeros -> smem: (s, -s*z) per (group, n); 512 coalesced elements
    {
        const int sbase = n0 * NGROUPS;
        #pragma unroll
        for (int jj = 0; jj < 4; ++jj) {
            const int i = tid * 4 + jj;          // 0..511
            const int n = i >> 5;
            const int g = i & 31;
            const float s = elt_to_f<DT>(scales, sbase + i);
            const float z = elt_to_f<DT>(zeros,  sbase + i);
            sh_p[g][n] = __halves2half2(__float2half(s), __float2half(-s * z));
        }
    }
    __syncthreads();

    float acc0[4] = {0.f, 0.f, 0.f, 0.f};
    float acc1[4] = {0.f, 0.f, 0.f, 0.f};

    // A fragment prefetch for stage 0 (chunks warp*32+0, warp*32+1)
    const int chunk0 = warp * 32;
    uint4 aN[4];
    aN[0] = __ldg(g_Aperm + chunk0 * 64 + lane);
    aN[1] = __ldg(g_Aperm + chunk0 * 64 + 32 + lane);
    aN[2] = __ldg(g_Aperm + (chunk0 + 1) * 64 + lane);
    aN[3] = __ldg(g_Aperm + (chunk0 + 1) * 64 + 32 + lane);

    #pragma unroll 1
    for (int s = 0; s < NSTAGE; ++s) {
        const int gg = warp * 8 + (s >> 1);        // 128-k group = 2 stages
        const __half2 p0 = sh_p[gg][r];
        const __half2 p1 = sh_p[gg][8 + r];
        const __half2 vs0  = __half2half2(__low2half(p0));
        const __half2 vmz0 = __half2half2(__high2half(p0));
        const __half2 vs1  = __half2half2(__low2half(p1));
        const __half2 vmz1 = __half2half2(__high2half(p1));

        cp_wait<QSTAGE - 2>();
        __syncwarp();

        // issue the next stage's cp.async IMMEDIATELY (slot consumed last iter)
        const int nx = s + QSTAGE - 1;
        if (nx < NSTAGE) {
            const uint32_t db = qsm + (nx & (QSTAGE - 1)) * STAGE_BYTES;
            #pragma unroll
            for (int j = 0; j < 4; ++j) cp16(db + dsto[j], srcp[j] + nx * 32);
        }
        cp_commit();

        // current A fragments; prefetch next stage's while MMAs run
        uint4 a0 = aN[0], a1 = aN[1], a2 = aN[2], a3 = aN[3];
        if (s < NSTAGE - 1) {
            const int cb = warp * 32 + (s + 1) * 2;
            aN[0] = __ldg(g_Aperm + cb * 64 + lane);
            aN[1] = __ldg(g_Aperm + cb * 64 + 32 + lane);
            aN[2] = __ldg(g_Aperm + (cb + 1) * 64 + lane);
            aN[3] = __ldg(g_Aperm + (cb + 1) * 64 + 32 + lane);
        }

        const uint32_t sb = qsm + (s & (QSTAGE - 1)) * STAGE_BYTES;

        #pragma unroll
        for (int kk = 0; kk < 2; ++kk) {
            const uint4 af0 = (kk == 0) ? a0 : a2;
            const uint4 af1 = (kk == 0) ? a1 : a3;

            const int slot = kk * 4 + t;
            const uint32_t sw = sb + (uint32_t)(slot * 256);
            const uint32_t rot = (uint32_t)((slot & 3) << 1);
            const uint4 q0 = lds128(sw + (((uint32_t)r ^ rot) << 4));        // col 0 (n=r)
            const uint4 q1 = lds128(sw + (((uint32_t)(8 + r) ^ rot) << 4));  // col 1 (n=8+r)

            {
                const uint32_t w0 = dq_word(dec_nib(q0.x), vs0, vmz0);
                const uint32_t w1 = dq_word(dec_nib(q0.y), vs0, vmz0);
                const uint32_t w2 = dq_word(dec_nib(q0.z), vs0, vmz0);
                const uint32_t w3 = dq_word(dec_nib(q0.w), vs0, vmz0);
                mma_16816(acc0, af0.x, af0.y, af0.z, af0.w, w0, w1);
                mma_16816(acc0, af1.x, af1.y, af1.z, af1.w, w2, w3);
            }
            {
                const uint32_t w0 = dq_word(dec_nib(q1.x), vs1, vmz1);
                const uint32_t w1 = dq_word(dec_nib(q1.y), vs1, vmz1);
                const uint32_t w2 = dq_word(dec_nib(q1.z), vs1, vmz1);
                const uint32_t w3 = dq_word(dec_nib(q1.w), vs1, vmz1);
                mma_16816(acc1, af0.x, af0.y, af0.z, af0.w, w0, w1);
                mma_16816(acc1, af1.x, af1.y, af1.z, af1.w, w2, w3);
            }
        }
    }

    // cross-warp reduction: C frag (m = r/r+8, n = c*8 + 2t, 2t+1)
    {
        sh_red[warp][r][2 * t]             = acc0[0];
        sh_red[warp][r][2 * t + 1]         = acc0[1];
        sh_red[warp][r + 8][2 * t]         = acc0[2];
        sh_red[warp][r + 8][2 * t + 1]     = acc0[3];
        sh_red[warp][r][8 + 2 * t]         = acc1[0];
        sh_red[warp][r][8 + 2 * t + 1]     = acc1[1];
        sh_red[warp][r + 8][8 + 2 * t]     = acc1[2];
        sh_red[warp][r + 8][8 + 2 * t + 1] = acc1[3];
    }
    __syncthreads();

    #pragma unroll
    for (int j = 0; j < 2; ++j) {
        const int idx = tid + j * 128;   // 0..255
        const int m  = idx >> 4;         // 0..15
        const int nl = idx & 15;         // 0..15
        float v = (sh_red[0][m][nl] + sh_red[1][m][nl]) + (sh_red[2][m][nl] + sh_red[3][m][nl]);
        v += elt_to_f<DT>(bias, n0 + nl);
        store_out<DT>(out, m * NDIM + n0 + nl, v);
    }
}

__global__ __launch_bounds__(128, 5)
void gptq_main_kernel(const int* __restrict__ qw,
                      const void* __restrict__ scales,
                      const void* __restrict__ zeros,
                      const void* __restrict__ bias,
                      void* __restrict__ out) {
    const int dt = g_dtype;
    if (dt == 1)      gptq_body<1>(qw, scales, zeros, bias, out);
    else if (dt == 0) gptq_body<0>(qw, scales, zeros, bias, out);
    else              gptq_body<2>(qw, scales, zeros, bias, out);
}

extern "C" void kernel_launch(void* const* d_in, const int* in_sizes, int n_in,
                              void* d_out, int out_size) {
    const void* A      = nullptr;
    const int*  qw     = nullptr;
    const void* scales = nullptr;
    const void* zeros  = nullptr;
    const void* bias   = nullptr;

    for (int i = 0; i < n_in; ++i) {
        const int sz = in_sizes[i];
        if (sz == MDIM * KDIM) {                    // 65536
            A = d_in[i];
        } else if (sz == NDIM * (KDIM / 2)) {       // 22544384
            qw = (const int*)d_in[i];
        } else if (sz == NDIM) {                    // 11008
            bias = d_in[i];
        } else if (sz == NDIM * NGROUPS) {          // 352256
            if (!scales) scales = d_in[i];
            else         zeros  = d_in[i];
        }
    }

    prep_kernel<<<NCHUNKS, 32>>>(A, scales);
    gptq_main_kernel<<<NDIM / NTILE, 128>>>(qw, scales, zeros, bias, d_out);
}